// round 9
// baseline (speedup 1.0000x reference)
#include <cuda_runtime.h>
#include <cuda_bf16.h>
#include <cuda_fp16.h>
#include <cstdint>

#define IN_F  256
#define OUT_F 128
#define MAX_N 50048
#define MAX_E 800000
#define BLD_NB 128         // builder blocks (< #SMs: co-residency guaranteed)
#define BLD_B  1024        // builder threads per block

// ---------------------------------------------------------------------------
// Scratch (static __device__ — no allocations allowed)
// ---------------------------------------------------------------------------
__device__ __align__(16) __half g_h[(size_t)MAX_N * OUT_F];  // normalized feats (fp16)
__device__ int   g_deg[MAX_N];
__device__ int   g_cnt[MAX_N];
__device__ int   g_off[MAX_N + 1];
__device__ int   g_pos[MAX_N];
__device__ int   g_srcs[MAX_E];
__device__ int   g_bsum[BLD_NB];
__device__ __align__(16) unsigned short g_w0[IN_F * OUT_F];
__device__ __align__(16) unsigned short g_w1[IN_F * OUT_F];
// grid barrier state (zero-init; arrive returns to 0 after each barrier)
__device__ unsigned g_bar_arrive;
__device__ volatile unsigned g_bar_gen;

// ---------------------------------------------------------------------------
__device__ __forceinline__ uint32_t smem_u32(const void* p) {
    uint32_t a;
    asm("{ .reg .u64 t; cvta.to.shared.u64 t, %1; cvt.u32.u64 %0, t; }" : "=r"(a) : "l"(p));
    return a;
}
__device__ __forceinline__ void ldm_x4(uint32_t* r, uint32_t addr) {
    asm volatile("ldmatrix.sync.aligned.m8n8.x4.shared.b16 {%0,%1,%2,%3}, [%4];"
                 : "=r"(r[0]), "=r"(r[1]), "=r"(r[2]), "=r"(r[3]) : "r"(addr));
}
__device__ __forceinline__ void ldm_x4_t(uint32_t* r, uint32_t addr) {
    asm volatile("ldmatrix.sync.aligned.m8n8.x4.trans.shared.b16 {%0,%1,%2,%3}, [%4];"
                 : "=r"(r[0]), "=r"(r[1]), "=r"(r[2]), "=r"(r[3]) : "r"(addr));
}
__device__ __forceinline__ void mma_bf16(float* d, const uint32_t* a, uint32_t b0, uint32_t b1) {
    asm volatile(
        "mma.sync.aligned.m16n8k16.row.col.f32.bf16.bf16.f32 "
        "{%0,%1,%2,%3}, {%4,%5,%6,%7}, {%8,%9}, {%0,%1,%2,%3};"
        : "+f"(d[0]), "+f"(d[1]), "+f"(d[2]), "+f"(d[3])
        : "r"(a[0]), "r"(a[1]), "r"(a[2]), "r"(a[3]), "r"(b0), "r"(b1));
}
__device__ __forceinline__ void split_bf16(float x, unsigned short& hi, unsigned short& lo) {
    __nv_bfloat16 h = __float2bfloat16_rn(x);
    float r = x - __bfloat162float(h);
    __nv_bfloat16 l = __float2bfloat16_rn(r);
    hi = __bfloat16_as_ushort(h);
    lo = __bfloat16_as_ushort(l);
}

// Grid-wide sense(generation)-reversal barrier. All BLD_NB blocks co-resident.
__device__ __forceinline__ void grid_barrier() {
    __syncthreads();
    if (threadIdx.x == 0) {
        unsigned gen = g_bar_gen;
        __threadfence();
        unsigned a = atomicAdd(&g_bar_arrive, 1u);
        if (a == BLD_NB - 1) {
            g_bar_arrive = 0;
            __threadfence();
            g_bar_gen = gen + 1;
        } else {
            while (g_bar_gen == gen) __nanosleep(32);
        }
    }
    __syncthreads();
}

// ---------------------------------------------------------------------------
// Kernel 1: fused CSR builder (zero + wsplit + histogram + scan + bucket)
// ---------------------------------------------------------------------------
__global__ void __launch_bounds__(BLD_B)
builder_kernel(const int* __restrict__ src, const int* __restrict__ dst,
               const float* __restrict__ weight, int N, int E) {
    const int tid = threadIdx.x;
    const int gt  = blockIdx.x * BLD_B + tid;
    const int gsz = BLD_NB * BLD_B;
    const int lane = tid & 31, w = tid >> 5;
    __shared__ int wsum[32];
    __shared__ int sbase;

    // ---- Phase 0: zero counters + split W ----
    for (int i = gt; i < N; i += gsz) { g_deg[i] = 0; g_cnt[i] = 0; }
    for (int i = gt; i < IN_F * OUT_F; i += gsz) {
        unsigned short hi, lo;
        split_bf16(weight[i], hi, lo);
        g_w0[i] = hi;
        g_w1[i] = lo;
    }
    grid_barrier();

    // ---- Phase 1: degree histograms ----
    for (int e = gt; e < E; e += gsz) {
        atomicAdd(&g_deg[src[e]], 1);
        atomicAdd(&g_cnt[dst[e]], 1);
    }
    grid_barrier();

    // ---- Phase 2: block-local exclusive scan of this block's chunk ----
    const int chunk = (N + BLD_NB - 1) / BLD_NB;     // 391 <= 1024
    const int beg = blockIdx.x * chunk;
    int i = beg + tid;
    int v = (tid < chunk && i < N) ? g_cnt[i] : 0;
    int inc = v;
#pragma unroll
    for (int o = 1; o < 32; o <<= 1) {
        int t = __shfl_up_sync(0xffffffffu, inc, o);
        if (lane >= o) inc += t;
    }
    if (lane == 31) wsum[w] = inc;
    __syncthreads();
    if (w == 0) {
        int x = wsum[lane];
#pragma unroll
        for (int o = 1; o < 32; o <<= 1) {
            int t = __shfl_up_sync(0xffffffffu, x, o);
            if (lane >= o) x += t;
        }
        wsum[lane] = x;
    }
    __syncthreads();
    int wbase = (w > 0) ? wsum[w - 1] : 0;
    int excl = wbase + inc - v;
    if (tid == BLD_B - 1) g_bsum[blockIdx.x] = wbase + inc;
    grid_barrier();

    // ---- Phase 3: block base = sum of preceding block totals; apply ----
    if (tid < 32) {
        int sum = 0;
        for (int b = tid; b < blockIdx.x; b += 32) sum += g_bsum[b];
#pragma unroll
        for (int o = 16; o > 0; o >>= 1)
            sum += __shfl_down_sync(0xffffffffu, sum, o);
        if (tid == 0) sbase = sum;
    }
    __syncthreads();
    if (tid < chunk && i < N) {
        int o = excl + sbase;
        g_off[i] = o;
        g_pos[i] = o;
    }
    if (gt == 0) g_off[N] = E;
    grid_barrier();

    // ---- Phase 4: bucket src ids by dst ----
    for (int e = gt; e < E; e += gsz) {
        int p = atomicAdd(&g_pos[dst[e]], 1);
        g_srcs[p] = src[e];
    }
}

// ---------------------------------------------------------------------------
// Kernel 2: HMMA GEMM  h = (feat @ W) * (1/max(deg,1))   (unchanged from R7)
// ---------------------------------------------------------------------------
#define KT 64
#define SA0 0
#define SA1 16384
#define SB0 32768
#define SB1 49152
#define BUF 65536
#define GEMM_SMEM (2 * BUF)

__device__ __forceinline__ void load_a_regs(float4* va, const float* __restrict__ feat,
                                            int block_row, int k0, int tid, int N) {
#pragma unroll
    for (int i = 0; i < 8; i++) {
        int idx = i * 256 + tid;
        int r   = idx >> 4;
        int c4  = idx & 15;
        int grow = block_row + r;
        va[i] = make_float4(0.f, 0.f, 0.f, 0.f);
        if (grow < N)
            va[i] = *(const float4*)(feat + (size_t)grow * IN_F + k0 + c4 * 4);
    }
}
__device__ __forceinline__ void load_b_regs(uint2* vb0, uint2* vb1, int k0, int tid) {
#pragma unroll
    for (int i = 0; i < 8; i++) {
        int idx = i * 256 + tid;
        int k   = idx >> 5;
        int c8  = idx & 31;
        vb0[i] = *(const uint2*)&g_w0[(k0 + k) * OUT_F + c8 * 4];
        vb1[i] = *(const uint2*)&g_w1[(k0 + k) * OUT_F + c8 * 4];
    }
}
__device__ __forceinline__ void store_a(char* buf, const float4* va, int tid) {
#pragma unroll
    for (int i = 0; i < 8; i++) {
        int idx = i * 256 + tid;
        int r   = idx >> 4;
        int c4  = idx & 15;
        float4 v = va[i];
        unsigned short h0, h1, h2, h3, l0, l1, l2, l3;
        split_bf16(v.x, h0, l0); split_bf16(v.y, h1, l1);
        split_bf16(v.z, h2, l2); split_bf16(v.w, h3, l3);
        uint2 hv, lv;
        hv.x = (uint32_t)h0 | ((uint32_t)h1 << 16);
        hv.y = (uint32_t)h2 | ((uint32_t)h3 << 16);
        lv.x = (uint32_t)l0 | ((uint32_t)l1 << 16);
        lv.y = (uint32_t)l2 | ((uint32_t)l3 << 16);
        int chunk = c4 >> 1, half = c4 & 1;
        uint32_t off = (uint32_t)r * 128 + (uint32_t)((chunk ^ (r & 7)) << 4) + half * 8;
        *(uint2*)(buf + SA0 + off) = hv;
        *(uint2*)(buf + SA1 + off) = lv;
    }
}
__device__ __forceinline__ void store_b(char* buf, const uint2* vb0, const uint2* vb1, int tid) {
#pragma unroll
    for (int i = 0; i < 8; i++) {
        int idx = i * 256 + tid;
        int k   = idx >> 5;
        int c8  = idx & 31;
        int chunk = c8 >> 1, half = c8 & 1;
        uint32_t off = (uint32_t)k * 256 + (uint32_t)((chunk ^ (k & 7)) << 4) + half * 8;
        *(uint2*)(buf + SB0 + off) = vb0[i];
        *(uint2*)(buf + SB1 + off) = vb1[i];
    }
}

__global__ void __launch_bounds__(256)
gemm_hmma_kernel(const float* __restrict__ feat, int N) {
    extern __shared__ char smem[];
    const uint32_t sb = smem_u32(smem);
    const int tid  = threadIdx.x;
    const int wid  = tid >> 5;
    const int lane = tid & 31;
    const int mw   = wid & 3;
    const int nw   = wid >> 2;
    const int block_row = blockIdx.x * 128;

    float acc[2][8][4];
#pragma unroll
    for (int mt = 0; mt < 2; mt++)
#pragma unroll
        for (int g = 0; g < 8; g++)
#pragma unroll
            for (int c = 0; c < 4; c++) acc[mt][g][c] = 0.f;

    float4 va[8];
    uint2 vb0[8], vb1[8];
    load_a_regs(va, feat, block_row, 0, tid, N);
    load_b_regs(vb0, vb1, 0, tid);
    store_a(smem, va, tid);
    store_b(smem, vb0, vb1, tid);
    __syncthreads();

    for (int pass = 0; pass < 4; pass++) {
        const uint32_t sbc = sb + (uint32_t)(pass & 1) * BUF;

        if (pass < 3) {
            load_a_regs(va, feat, block_row, (pass + 1) * KT, tid, N);
            load_b_regs(vb0, vb1, (pass + 1) * KT, tid);
        }

#pragma unroll
        for (int ks = 0; ks < 4; ks++) {
            uint32_t a0[2][4], a1[2][4];
#pragma unroll
            for (int mt = 0; mt < 2; mt++) {
                int row = mw * 32 + mt * 16 + (lane & 15);
                int chunk = ks * 2 + (lane >> 4);
                uint32_t off = (uint32_t)row * 128 + (uint32_t)((chunk ^ (row & 7)) << 4);
                ldm_x4(a0[mt], sbc + SA0 + off);
                ldm_x4(a1[mt], sbc + SA1 + off);
            }
            uint32_t b0[8][2], b1[8][2];
#pragma unroll
            for (int g16 = 0; g16 < 4; g16++) {
                int t = lane >> 3;
                int krow = ks * 16 + ((t & 1) << 3) + (lane & 7);
                int chunk = nw * 8 + g16 * 2 + (t >> 1);
                uint32_t off = (uint32_t)krow * 256 + (uint32_t)((chunk ^ (krow & 7)) << 4);
                uint32_t r0[4], r1[4];
                ldm_x4_t(r0, sbc + SB0 + off);
                ldm_x4_t(r1, sbc + SB1 + off);
                b0[g16 * 2 + 0][0] = r0[0]; b0[g16 * 2 + 0][1] = r0[1];
                b0[g16 * 2 + 1][0] = r0[2]; b0[g16 * 2 + 1][1] = r0[3];
                b1[g16 * 2 + 0][0] = r1[0]; b1[g16 * 2 + 0][1] = r1[1];
                b1[g16 * 2 + 1][0] = r1[2]; b1[g16 * 2 + 1][1] = r1[3];
            }
#pragma unroll
            for (int mt = 0; mt < 2; mt++)
#pragma unroll
                for (int g = 0; g < 8; g++) {
                    mma_bf16(acc[mt][g], a0[mt], b0[g][0], b0[g][1]);
                    mma_bf16(acc[mt][g], a0[mt], b1[g][0], b1[g][1]);
                    mma_bf16(acc[mt][g], a1[mt], b0[g][0], b0[g][1]);
                }
        }

        if (pass < 3) {
            char* nxt = smem + ((pass + 1) & 1) * BUF;
            store_a(nxt, va, tid);
            store_b(nxt, vb0, vb1, tid);
        }
        __syncthreads();
    }

#pragma unroll
    for (int mt = 0; mt < 2; mt++) {
        int row0 = block_row + mw * 32 + mt * 16 + (lane >> 2);
        int row1 = row0 + 8;
        float n0 = (row0 < N) ? 1.0f / fmaxf((float)g_deg[row0], 1.0f) : 0.f;
        float n1 = (row1 < N) ? 1.0f / fmaxf((float)g_deg[row1], 1.0f) : 0.f;
#pragma unroll
        for (int g = 0; g < 8; g++) {
            int col = nw * 64 + g * 8 + (lane & 3) * 2;
            if (row0 < N)
                *(__half2*)(g_h + (size_t)row0 * OUT_F + col) =
                    __floats2half2_rn(acc[mt][g][0] * n0, acc[mt][g][1] * n0);
            if (row1 < N)
                *(__half2*)(g_h + (size_t)row1 * OUT_F + col) =
                    __floats2half2_rn(acc[mt][g][2] * n1, acc[mt][g][3] * n1);
        }
    }
}

// ---------------------------------------------------------------------------
// Kernel 3: gather  out[n] = sum_{e: dst=n} h[src[e]] + bias   (one warp/node)
// ---------------------------------------------------------------------------
__device__ __forceinline__ void acc_row(float4& acc, int s, int lane) {
    uint2 u = *((const uint2*)(g_h + (size_t)s * OUT_F) + lane);
    float2 f0 = __half22float2(*(__half2*)&u.x);
    float2 f1 = __half22float2(*(__half2*)&u.y);
    acc.x += f0.x; acc.y += f0.y; acc.z += f1.x; acc.w += f1.y;
}

__global__ void __launch_bounds__(256)
gather_kernel(const float* __restrict__ bias, float* __restrict__ out, int N) {
    const int lane = threadIdx.x & 31;
    const int node = (blockIdx.x * blockDim.x + threadIdx.x) >> 5;
    if (node >= N) return;
    const int beg = g_off[node];
    const int end = g_off[node + 1];

    float4 acc = make_float4(0.f, 0.f, 0.f, 0.f);
    for (int b = beg; b < end; b += 32) {
        int idx = b + lane;
        int s = (idx < end) ? g_srcs[idx] : 0;
        int cnt = end - b; if (cnt > 32) cnt = 32;
        int j = 0;
        for (; j + 4 <= cnt; j += 4) {
            int s0 = __shfl_sync(0xffffffffu, s, j + 0);
            int s1 = __shfl_sync(0xffffffffu, s, j + 1);
            int s2 = __shfl_sync(0xffffffffu, s, j + 2);
            int s3 = __shfl_sync(0xffffffffu, s, j + 3);
            acc_row(acc, s0, lane);
            acc_row(acc, s1, lane);
            acc_row(acc, s2, lane);
            acc_row(acc, s3, lane);
        }
        for (; j < cnt; j++) {
            int sj = __shfl_sync(0xffffffffu, s, j);
            acc_row(acc, sj, lane);
        }
    }
    float4 b4 = *((const float4*)bias + lane);
    *((float4*)(out + (size_t)node * OUT_F) + lane) =
        make_float4(acc.x + b4.x, acc.y + b4.y, acc.z + b4.z, acc.w + b4.w);
}

// ---------------------------------------------------------------------------
extern "C" void kernel_launch(void* const* d_in, const int* in_sizes, int n_in,
                              void* d_out, int out_size) {
    const float* feat   = (const float*)d_in[0];
    const float* weight = (const float*)d_in[1];
    const float* bias   = (const float*)d_in[2];
    const int*   src    = (const int*)d_in[3];
    const int*   dst    = (const int*)d_in[4];
    float* out = (float*)d_out;

    const int N = in_sizes[0] / IN_F;   // 50000
    const int E = in_sizes[3];          // 800000

    cudaFuncSetAttribute(gemm_hmma_kernel,
                         cudaFuncAttributeMaxDynamicSharedMemorySize, GEMM_SMEM);

    builder_kernel<<<BLD_NB, BLD_B>>>(src, dst, weight, N, E);
    gemm_hmma_kernel<<<(N + 127) / 128, 256, GEMM_SMEM>>>(feat, N);
    gather_kernel<<<(N * 32 + 255) / 256, 256>>>(bias, out, N);
}

// round 11
// speedup vs baseline: 1.1017x; 1.1017x over previous
#include <cuda_runtime.h>
#include <cuda_bf16.h>
#include <cuda_fp16.h>
#include <cstdint>

#define IN_F  256
#define OUT_F 128
#define MAX_N 50048
#define MAX_E 800000
#define SCAN_B 1024
#define SCAN_NB ((MAX_N + SCAN_B - 1) / SCAN_B)   // 49

// ---------------------------------------------------------------------------
// Scratch (static __device__ — no allocations allowed)
// ---------------------------------------------------------------------------
__device__ __align__(16) __half g_h[(size_t)MAX_N * OUT_F];  // UNnormalized feats (fp16)
__device__ int   g_deg[MAX_N];
__device__ float g_norm[MAX_N];
__device__ int   g_cnt[MAX_N];
__device__ int   g_off[MAX_N + 1];
__device__ int   g_pos[MAX_N];
__device__ int   g_srcs[MAX_E];
__device__ int   g_bsum[SCAN_NB];

// ---------------------------------------------------------------------------
__device__ __forceinline__ uint32_t smem_u32(const void* p) {
    uint32_t a;
    asm("{ .reg .u64 t; cvta.to.shared.u64 t, %1; cvt.u32.u64 %0, t; }" : "=r"(a) : "l"(p));
    return a;
}
__device__ __forceinline__ void ldm_x4(uint32_t* r, uint32_t addr) {
    asm volatile("ldmatrix.sync.aligned.m8n8.x4.shared.b16 {%0,%1,%2,%3}, [%4];"
                 : "=r"(r[0]), "=r"(r[1]), "=r"(r[2]), "=r"(r[3]) : "r"(addr));
}
__device__ __forceinline__ void ldm_x4_t(uint32_t* r, uint32_t addr) {
    asm volatile("ldmatrix.sync.aligned.m8n8.x4.trans.shared.b16 {%0,%1,%2,%3}, [%4];"
                 : "=r"(r[0]), "=r"(r[1]), "=r"(r[2]), "=r"(r[3]) : "r"(addr));
}
__device__ __forceinline__ void mma_bf16(float* d, const uint32_t* a, uint32_t b0, uint32_t b1) {
    asm volatile(
        "mma.sync.aligned.m16n8k16.row.col.f32.bf16.bf16.f32 "
        "{%0,%1,%2,%3}, {%4,%5,%6,%7}, {%8,%9}, {%0,%1,%2,%3};"
        : "+f"(d[0]), "+f"(d[1]), "+f"(d[2]), "+f"(d[3])
        : "r"(a[0]), "r"(a[1]), "r"(a[2]), "r"(a[3]), "r"(b0), "r"(b1));
}
__device__ __forceinline__ void split_bf16(float x, unsigned short& hi, unsigned short& lo) {
    __nv_bfloat16 h = __float2bfloat16_rn(x);
    float r = x - __bfloat162float(h);
    __nv_bfloat16 l = __float2bfloat16_rn(r);
    hi = __bfloat16_as_ushort(h);
    lo = __bfloat16_as_ushort(l);
}

// ---------------------------------------------------------------------------
// streamB Kernel 1: zero counters
// ---------------------------------------------------------------------------
__global__ void zero_kernel(int N) {
    int stride = gridDim.x * blockDim.x;
    int tid = blockIdx.x * blockDim.x + threadIdx.x;
    for (int i = tid; i < N; i += stride) { g_deg[i] = 0; g_cnt[i] = 0; }
}

// ---------------------------------------------------------------------------
// streamB Kernel 2: out-degree(src) + in-degree(dst)
// ---------------------------------------------------------------------------
__global__ void edge_count_kernel(const int* __restrict__ src,
                                  const int* __restrict__ dst, int E) {
    int stride = gridDim.x * blockDim.x;
    for (int e = blockIdx.x * blockDim.x + threadIdx.x; e < E; e += stride) {
        atomicAdd(&g_deg[src[e]], 1);
        atomicAdd(&g_cnt[dst[e]], 1);
    }
}

// ---------------------------------------------------------------------------
// streamB Kernel 3: per-block exclusive scan of g_cnt + block totals + norm
// ---------------------------------------------------------------------------
__global__ void __launch_bounds__(SCAN_B)
scanA_kernel(int N) {
    __shared__ int wsum[32];
    int i = blockIdx.x * SCAN_B + threadIdx.x;
    int lane = threadIdx.x & 31, w = threadIdx.x >> 5;
    if (i < N) g_norm[i] = 1.0f / fmaxf((float)g_deg[i], 1.0f);
    int v = (i < N) ? g_cnt[i] : 0;
    int inc = v;
#pragma unroll
    for (int o = 1; o < 32; o <<= 1) {
        int t = __shfl_up_sync(0xffffffffu, inc, o);
        if (lane >= o) inc += t;
    }
    if (lane == 31) wsum[w] = inc;
    __syncthreads();
    if (w == 0) {
        int x = wsum[lane];
#pragma unroll
        for (int o = 1; o < 32; o <<= 1) {
            int t = __shfl_up_sync(0xffffffffu, x, o);
            if (lane >= o) x += t;
        }
        wsum[lane] = x;
    }
    __syncthreads();
    int base = (w > 0) ? wsum[w - 1] : 0;
    int excl = base + inc - v;
    if (i < N) g_off[i] = excl;
    if (threadIdx.x == SCAN_B - 1) g_bsum[blockIdx.x] = base + inc;
}

// ---------------------------------------------------------------------------
// streamB Kernel 4: add block bases (inline reduce of g_bsum); mirror to g_pos
// ---------------------------------------------------------------------------
__global__ void __launch_bounds__(SCAN_B)
scanC_kernel(int N, int E) {
    __shared__ int sbase;
    if (threadIdx.x < 32) {
        int sum = 0;
        for (int b = threadIdx.x; b < blockIdx.x; b += 32) sum += g_bsum[b];
#pragma unroll
        for (int o = 16; o > 0; o >>= 1)
            sum += __shfl_down_sync(0xffffffffu, sum, o);
        if (threadIdx.x == 0) sbase = sum;
    }
    __syncthreads();
    int i = blockIdx.x * SCAN_B + threadIdx.x;
    if (i < N) {
        int o = g_off[i] + sbase;
        g_off[i] = o;
        g_pos[i] = o;
    }
    if (i == 0) g_off[N] = E;
}

// ---------------------------------------------------------------------------
// streamB Kernel 5: bucket src ids by dst
// ---------------------------------------------------------------------------
__global__ void bucket_kernel(const int* __restrict__ src,
                              const int* __restrict__ dst, int E) {
    int stride = gridDim.x * blockDim.x;
    for (int e = blockIdx.x * blockDim.x + threadIdx.x; e < E; e += stride) {
        int p = atomicAdd(&g_pos[dst[e]], 1);
        g_srcs[p] = src[e];
    }
}

// ---------------------------------------------------------------------------
// streamA Kernel: HMMA GEMM  h = feat @ W  (UNnormalized, fp16 out).
// W split from fp32 inline (same byte traffic as pre-split bf16 pair).
// Double-buffered smem, one __syncthreads per K-pass.
// ---------------------------------------------------------------------------
#define KT 64
#define SA0 0
#define SA1 16384
#define SB0 32768
#define SB1 49152
#define BUF 65536
#define GEMM_SMEM (2 * BUF)

__device__ __forceinline__ void load_a_regs(float4* va, const float* __restrict__ feat,
                                            int block_row, int k0, int tid, int N) {
#pragma unroll
    for (int i = 0; i < 8; i++) {
        int idx = i * 256 + tid;
        int r   = idx >> 4;
        int c4  = idx & 15;
        int grow = block_row + r;
        va[i] = make_float4(0.f, 0.f, 0.f, 0.f);
        if (grow < N)
            va[i] = *(const float4*)(feat + (size_t)grow * IN_F + k0 + c4 * 4);
    }
}
__device__ __forceinline__ void load_b_regs(float4* vbw, const float* __restrict__ weight,
                                            int k0, int tid) {
#pragma unroll
    for (int i = 0; i < 8; i++) {
        int idx = i * 256 + tid;
        int k   = idx >> 5;
        int c8  = idx & 31;
        vbw[i] = *(const float4*)(weight + (size_t)(k0 + k) * OUT_F + c8 * 4);
    }
}
__device__ __forceinline__ void split4(float4 v, uint2& hv, uint2& lv) {
    unsigned short h0, h1, h2, h3, l0, l1, l2, l3;
    split_bf16(v.x, h0, l0); split_bf16(v.y, h1, l1);
    split_bf16(v.z, h2, l2); split_bf16(v.w, h3, l3);
    hv.x = (uint32_t)h0 | ((uint32_t)h1 << 16);
    hv.y = (uint32_t)h2 | ((uint32_t)h3 << 16);
    lv.x = (uint32_t)l0 | ((uint32_t)l1 << 16);
    lv.y = (uint32_t)l2 | ((uint32_t)l3 << 16);
}
__device__ __forceinline__ void store_a(char* buf, const float4* va, int tid) {
#pragma unroll
    for (int i = 0; i < 8; i++) {
        int idx = i * 256 + tid;
        int r   = idx >> 4;
        int c4  = idx & 15;
        uint2 hv, lv;
        split4(va[i], hv, lv);
        int chunk = c4 >> 1, half = c4 & 1;
        uint32_t off = (uint32_t)r * 128 + (uint32_t)((chunk ^ (r & 7)) << 4) + half * 8;
        *(uint2*)(buf + SA0 + off) = hv;
        *(uint2*)(buf + SA1 + off) = lv;
    }
}
__device__ __forceinline__ void store_b(char* buf, const float4* vbw, int tid) {
#pragma unroll
    for (int i = 0; i < 8; i++) {
        int idx = i * 256 + tid;
        int k   = idx >> 5;
        int c8  = idx & 31;
        uint2 hv, lv;
        split4(vbw[i], hv, lv);
        int chunk = c8 >> 1, half = c8 & 1;
        uint32_t off = (uint32_t)k * 256 + (uint32_t)((chunk ^ (k & 7)) << 4) + half * 8;
        *(uint2*)(buf + SB0 + off) = hv;
        *(uint2*)(buf + SB1 + off) = lv;
    }
}

__global__ void __launch_bounds__(256)
gemm_hmma_kernel(const float* __restrict__ feat, const float* __restrict__ weight, int N) {
    extern __shared__ char smem[];
    const uint32_t sb = smem_u32(smem);
    const int tid  = threadIdx.x;
    const int wid  = tid >> 5;
    const int lane = tid & 31;
    const int mw   = wid & 3;
    const int nw   = wid >> 2;
    const int block_row = blockIdx.x * 128;

    float acc[2][8][4];
#pragma unroll
    for (int mt = 0; mt < 2; mt++)
#pragma unroll
        for (int g = 0; g < 8; g++)
#pragma unroll
            for (int c = 0; c < 4; c++) acc[mt][g][c] = 0.f;

    float4 va[8], vbw[8];
    load_a_regs(va, feat, block_row, 0, tid, N);
    load_b_regs(vbw, weight, 0, tid);
    store_a(smem, va, tid);
    store_b(smem, vbw, tid);
    __syncthreads();

    for (int pass = 0; pass < 4; pass++) {
        const uint32_t sbc = sb + (uint32_t)(pass & 1) * BUF;

        if (pass < 3) {
            load_a_regs(va, feat, block_row, (pass + 1) * KT, tid, N);
            load_b_regs(vbw, weight, (pass + 1) * KT, tid);
        }

#pragma unroll
        for (int ks = 0; ks < 4; ks++) {
            uint32_t a0[2][4], a1[2][4];
#pragma unroll
            for (int mt = 0; mt < 2; mt++) {
                int row = mw * 32 + mt * 16 + (lane & 15);
                int chunk = ks * 2 + (lane >> 4);
                uint32_t off = (uint32_t)row * 128 + (uint32_t)((chunk ^ (row & 7)) << 4);
                ldm_x4(a0[mt], sbc + SA0 + off);
                ldm_x4(a1[mt], sbc + SA1 + off);
            }
            uint32_t b0[8][2], b1[8][2];
#pragma unroll
            for (int g16 = 0; g16 < 4; g16++) {
                int t = lane >> 3;
                int krow = ks * 16 + ((t & 1) << 3) + (lane & 7);
                int chunk = nw * 8 + g16 * 2 + (t >> 1);
                uint32_t off = (uint32_t)krow * 256 + (uint32_t)((chunk ^ (krow & 7)) << 4);
                uint32_t r0[4], r1[4];
                ldm_x4_t(r0, sbc + SB0 + off);
                ldm_x4_t(r1, sbc + SB1 + off);
                b0[g16 * 2 + 0][0] = r0[0]; b0[g16 * 2 + 0][1] = r0[1];
                b0[g16 * 2 + 1][0] = r0[2]; b0[g16 * 2 + 1][1] = r0[3];
                b1[g16 * 2 + 0][0] = r1[0]; b1[g16 * 2 + 0][1] = r1[1];
                b1[g16 * 2 + 1][0] = r1[2]; b1[g16 * 2 + 1][1] = r1[3];
            }
#pragma unroll
            for (int mt = 0; mt < 2; mt++)
#pragma unroll
                for (int g = 0; g < 8; g++) {
                    mma_bf16(acc[mt][g], a0[mt], b0[g][0], b0[g][1]);
                    mma_bf16(acc[mt][g], a0[mt], b1[g][0], b1[g][1]);
                    mma_bf16(acc[mt][g], a1[mt], b0[g][0], b0[g][1]);
                }
        }

        if (pass < 3) {
            char* nxt = smem + ((pass + 1) & 1) * BUF;
            store_a(nxt, va, tid);
            store_b(nxt, vbw, tid);
        }
        __syncthreads();
    }

    // ---- epilogue: store UNnormalized fp16 h ----
#pragma unroll
    for (int mt = 0; mt < 2; mt++) {
        int row0 = block_row + mw * 32 + mt * 16 + (lane >> 2);
        int row1 = row0 + 8;
#pragma unroll
        for (int g = 0; g < 8; g++) {
            int col = nw * 64 + g * 8 + (lane & 3) * 2;
            if (row0 < N)
                *(__half2*)(g_h + (size_t)row0 * OUT_F + col) =
                    __floats2half2_rn(acc[mt][g][0], acc[mt][g][1]);
            if (row1 < N)
                *(__half2*)(g_h + (size_t)row1 * OUT_F + col) =
                    __floats2half2_rn(acc[mt][g][2], acc[mt][g][3]);
        }
    }
}

// ---------------------------------------------------------------------------
// Join Kernel: gather  out[n] = sum_{e: dst=n} h[src[e]]*norm[src[e]] + bias
// ---------------------------------------------------------------------------
__device__ __forceinline__ void acc_row(float4& acc, int s, int lane) {
    float nrm = g_norm[s];
    uint2 u = *((const uint2*)(g_h + (size_t)s * OUT_F) + lane);
    float2 f0 = __half22float2(*(__half2*)&u.x);
    float2 f1 = __half22float2(*(__half2*)&u.y);
    acc.x += f0.x * nrm; acc.y += f0.y * nrm;
    acc.z += f1.x * nrm; acc.w += f1.y * nrm;
}

__global__ void __launch_bounds__(256)
gather_kernel(const float* __restrict__ bias, float* __restrict__ out, int N) {
    const int lane = threadIdx.x & 31;
    const int node = (blockIdx.x * blockDim.x + threadIdx.x) >> 5;
    if (node >= N) return;
    const int beg = g_off[node];
    const int end = g_off[node + 1];

    float4 acc = make_float4(0.f, 0.f, 0.f, 0.f);
    for (int b = beg; b < end; b += 32) {
        int idx = b + lane;
        int s = (idx < end) ? g_srcs[idx] : 0;
        int cnt = end - b; if (cnt > 32) cnt = 32;
        int j = 0;
        for (; j + 4 <= cnt; j += 4) {
            int s0 = __shfl_sync(0xffffffffu, s, j + 0);
            int s1 = __shfl_sync(0xffffffffu, s, j + 1);
            int s2 = __shfl_sync(0xffffffffu, s, j + 2);
            int s3 = __shfl_sync(0xffffffffu, s, j + 3);
            acc_row(acc, s0, lane);
            acc_row(acc, s1, lane);
            acc_row(acc, s2, lane);
            acc_row(acc, s3, lane);
        }
        for (; j < cnt; j++) {
            int sj = __shfl_sync(0xffffffffu, s, j);
            acc_row(acc, sj, lane);
        }
    }
    float4 b4 = *((const float4*)bias + lane);
    *((float4*)(out + (size_t)node * OUT_F) + lane) =
        make_float4(acc.x + b4.x, acc.y + b4.y, acc.z + b4.z, acc.w + b4.w);
}

// ---------------------------------------------------------------------------
extern "C" void kernel_launch(void* const* d_in, const int* in_sizes, int n_in,
                              void* d_out, int out_size) {
    const float* feat   = (const float*)d_in[0];
    const float* weight = (const float*)d_in[1];
    const float* bias   = (const float*)d_in[2];
    const int*   src    = (const int*)d_in[3];
    const int*   dst    = (const int*)d_in[4];
    float* out = (float*)d_out;

    const int N = in_sizes[0] / IN_F;   // 50000
    const int E = in_sizes[3];          // 800000
    const int nb = (N + SCAN_B - 1) / SCAN_B;

    // One-time resource setup (host-side objects only; no device memory).
    static cudaStream_t sB = nullptr;
    static cudaEvent_t evFork = nullptr, evCSR = nullptr;
    if (sB == nullptr) {
        cudaStreamCreateWithFlags(&sB, cudaStreamNonBlocking);
        cudaEventCreateWithFlags(&evFork, cudaEventDisableTiming);
        cudaEventCreateWithFlags(&evCSR, cudaEventDisableTiming);
        cudaFuncSetAttribute(gemm_hmma_kernel,
                             cudaFuncAttributeMaxDynamicSharedMemorySize, GEMM_SMEM);
    }

    // Fork: CSR chain on sB, GEMM on the capture (default) stream.
    cudaEventRecord(evFork, 0);
    cudaStreamWaitEvent(sB, evFork, 0);

    zero_kernel<<<256, 256, 0, sB>>>(N);
    edge_count_kernel<<<512, 256, 0, sB>>>(src, dst, E);
    scanA_kernel<<<nb, SCAN_B, 0, sB>>>(N);
    scanC_kernel<<<nb, SCAN_B, 0, sB>>>(N, E);
    bucket_kernel<<<512, 256, 0, sB>>>(src, dst, E);
    cudaEventRecord(evCSR, sB);

    gemm_hmma_kernel<<<(N + 127) / 128, 256, GEMM_SMEM>>>(feat, weight, N);

    // Join: gather needs g_h (stream 0) + CSR/norm (sB).
    cudaStreamWaitEvent(0, evCSR, 0);
    gather_kernel<<<(N * 32 + 255) / 256, 256>>>(bias, out, N);
}

// round 12
// speedup vs baseline: 1.1252x; 1.0213x over previous
#include <cuda_runtime.h>
#include <cuda_bf16.h>
#include <cuda_fp16.h>
#include <cstdint>

#define IN_F  256
#define OUT_F 128
#define MAX_N 50048
#define MAX_E 800000
#define SCAN_B 1024

// ---------------------------------------------------------------------------
// Scratch (static __device__ — no allocations allowed)
// ---------------------------------------------------------------------------
__device__ __align__(16) __half g_h[(size_t)MAX_N * OUT_F];  // UNnormalized feats (fp16)
__device__ int   g_deg[MAX_N];
__device__ float g_norm[MAX_N];
__device__ int   g_cnt[MAX_N];
__device__ int   g_off[MAX_N];                 // segment start per node (order-free slabs)
__device__ int   g_pos[MAX_N];
__device__ int   g_srcs[MAX_E];
__device__ int   g_total;                      // slab cursor

// ---------------------------------------------------------------------------
__device__ __forceinline__ uint32_t smem_u32(const void* p) {
    uint32_t a;
    asm("{ .reg .u64 t; cvta.to.shared.u64 t, %1; cvt.u32.u64 %0, t; }" : "=r"(a) : "l"(p));
    return a;
}
__device__ __forceinline__ void ldm_x4(uint32_t* r, uint32_t addr) {
    asm volatile("ldmatrix.sync.aligned.m8n8.x4.shared.b16 {%0,%1,%2,%3}, [%4];"
                 : "=r"(r[0]), "=r"(r[1]), "=r"(r[2]), "=r"(r[3]) : "r"(addr));
}
__device__ __forceinline__ void ldm_x4_t(uint32_t* r, uint32_t addr) {
    asm volatile("ldmatrix.sync.aligned.m8n8.x4.trans.shared.b16 {%0,%1,%2,%3}, [%4];"
                 : "=r"(r[0]), "=r"(r[1]), "=r"(r[2]), "=r"(r[3]) : "r"(addr));
}
__device__ __forceinline__ void mma_bf16(float* d, const uint32_t* a, uint32_t b0, uint32_t b1) {
    asm volatile(
        "mma.sync.aligned.m16n8k16.row.col.f32.bf16.bf16.f32 "
        "{%0,%1,%2,%3}, {%4,%5,%6,%7}, {%8,%9}, {%0,%1,%2,%3};"
        : "+f"(d[0]), "+f"(d[1]), "+f"(d[2]), "+f"(d[3])
        : "r"(a[0]), "r"(a[1]), "r"(a[2]), "r"(a[3]), "r"(b0), "r"(b1));
}
__device__ __forceinline__ void split_bf16(float x, unsigned short& hi, unsigned short& lo) {
    __nv_bfloat16 h = __float2bfloat16_rn(x);
    float r = x - __bfloat162float(h);
    __nv_bfloat16 l = __float2bfloat16_rn(r);
    hi = __bfloat16_as_ushort(h);
    lo = __bfloat16_as_ushort(l);
}

// ---------------------------------------------------------------------------
// streamB Kernel 1: zero counters + slab cursor
// ---------------------------------------------------------------------------
__global__ void zero_kernel(int N) {
    int stride = gridDim.x * blockDim.x;
    int tid = blockIdx.x * blockDim.x + threadIdx.x;
    for (int i = tid; i < N; i += stride) { g_deg[i] = 0; g_cnt[i] = 0; }
    if (tid == 0) g_total = 0;
}

// ---------------------------------------------------------------------------
// streamB Kernel 2: out-degree(src) + in-degree(dst)
// ---------------------------------------------------------------------------
__global__ void edge_count_kernel(const int* __restrict__ src,
                                  const int* __restrict__ dst, int E) {
    int stride = gridDim.x * blockDim.x;
    for (int e = blockIdx.x * blockDim.x + threadIdx.x; e < E; e += stride) {
        atomicAdd(&g_deg[src[e]], 1);
        atomicAdd(&g_cnt[dst[e]], 1);
    }
}

// ---------------------------------------------------------------------------
// streamB Kernel 3: fused scan — norm + block-local exclusive scan of g_cnt,
// block claims its slab via one atomicAdd on the global cursor (order-free
// CSR: segments contiguous & disjoint, but block slabs in arbitrary order).
// ---------------------------------------------------------------------------
__global__ void __launch_bounds__(SCAN_B)
scan_kernel(int N) {
    __shared__ int wsum[32];
    __shared__ int sbase;
    int i = blockIdx.x * SCAN_B + threadIdx.x;
    int lane = threadIdx.x & 31, w = threadIdx.x >> 5;
    if (i < N) g_norm[i] = 1.0f / fmaxf((float)g_deg[i], 1.0f);
    int v = (i < N) ? g_cnt[i] : 0;
    int inc = v;
#pragma unroll
    for (int o = 1; o < 32; o <<= 1) {
        int t = __shfl_up_sync(0xffffffffu, inc, o);
        if (lane >= o) inc += t;
    }
    if (lane == 31) wsum[w] = inc;
    __syncthreads();
    if (w == 0) {
        int x = wsum[lane];
#pragma unroll
        for (int o = 1; o < 32; o <<= 1) {
            int t = __shfl_up_sync(0xffffffffu, x, o);
            if (lane >= o) x += t;
        }
        wsum[lane] = x;
    }
    __syncthreads();
    int base = (w > 0) ? wsum[w - 1] : 0;
    int excl = base + inc - v;
    if (threadIdx.x == SCAN_B - 1) sbase = atomicAdd(&g_total, base + inc);
    __syncthreads();
    if (i < N) {
        int o = excl + sbase;
        g_off[i] = o;
        g_pos[i] = o;
    }
}

// ---------------------------------------------------------------------------
// streamB Kernel 4: bucket src ids by dst
// ---------------------------------------------------------------------------
__global__ void bucket_kernel(const int* __restrict__ src,
                              const int* __restrict__ dst, int E) {
    int stride = gridDim.x * blockDim.x;
    for (int e = blockIdx.x * blockDim.x + threadIdx.x; e < E; e += stride) {
        int p = atomicAdd(&g_pos[dst[e]], 1);
        g_srcs[p] = src[e];
    }
}

// ---------------------------------------------------------------------------
// streamA Kernel: HMMA GEMM  h = feat @ W  (UNnormalized, fp16 out).
// ---------------------------------------------------------------------------
#define KT 64
#define SA0 0
#define SA1 16384
#define SB0 32768
#define SB1 49152
#define BUF 65536
#define GEMM_SMEM (2 * BUF)

__device__ __forceinline__ void load_a_regs(float4* va, const float* __restrict__ feat,
                                            int block_row, int k0, int tid, int N) {
#pragma unroll
    for (int i = 0; i < 8; i++) {
        int idx = i * 256 + tid;
        int r   = idx >> 4;
        int c4  = idx & 15;
        int grow = block_row + r;
        va[i] = make_float4(0.f, 0.f, 0.f, 0.f);
        if (grow < N)
            va[i] = *(const float4*)(feat + (size_t)grow * IN_F + k0 + c4 * 4);
    }
}
__device__ __forceinline__ void load_b_regs(float4* vbw, const float* __restrict__ weight,
                                            int k0, int tid) {
#pragma unroll
    for (int i = 0; i < 8; i++) {
        int idx = i * 256 + tid;
        int k   = idx >> 5;
        int c8  = idx & 31;
        vbw[i] = *(const float4*)(weight + (size_t)(k0 + k) * OUT_F + c8 * 4);
    }
}
__device__ __forceinline__ void split4(float4 v, uint2& hv, uint2& lv) {
    unsigned short h0, h1, h2, h3, l0, l1, l2, l3;
    split_bf16(v.x, h0, l0); split_bf16(v.y, h1, l1);
    split_bf16(v.z, h2, l2); split_bf16(v.w, h3, l3);
    hv.x = (uint32_t)h0 | ((uint32_t)h1 << 16);
    hv.y = (uint32_t)h2 | ((uint32_t)h3 << 16);
    lv.x = (uint32_t)l0 | ((uint32_t)l1 << 16);
    lv.y = (uint32_t)l2 | ((uint32_t)l3 << 16);
}
__device__ __forceinline__ void store_a(char* buf, const float4* va, int tid) {
#pragma unroll
    for (int i = 0; i < 8; i++) {
        int idx = i * 256 + tid;
        int r   = idx >> 4;
        int c4  = idx & 15;
        uint2 hv, lv;
        split4(va[i], hv, lv);
        int chunk = c4 >> 1, half = c4 & 1;
        uint32_t off = (uint32_t)r * 128 + (uint32_t)((chunk ^ (r & 7)) << 4) + half * 8;
        *(uint2*)(buf + SA0 + off) = hv;
        *(uint2*)(buf + SA1 + off) = lv;
    }
}
__device__ __forceinline__ void store_b(char* buf, const float4* vbw, int tid) {
#pragma unroll
    for (int i = 0; i < 8; i++) {
        int idx = i * 256 + tid;
        int k   = idx >> 5;
        int c8  = idx & 31;
        uint2 hv, lv;
        split4(vbw[i], hv, lv);
        int chunk = c8 >> 1, half = c8 & 1;
        uint32_t off = (uint32_t)k * 256 + (uint32_t)((chunk ^ (k & 7)) << 4) + half * 8;
        *(uint2*)(buf + SB0 + off) = hv;
        *(uint2*)(buf + SB1 + off) = lv;
    }
}

__global__ void __launch_bounds__(256)
gemm_hmma_kernel(const float* __restrict__ feat, const float* __restrict__ weight, int N) {
    extern __shared__ char smem[];
    const uint32_t sb = smem_u32(smem);
    const int tid  = threadIdx.x;
    const int wid  = tid >> 5;
    const int lane = tid & 31;
    const int mw   = wid & 3;
    const int nw   = wid >> 2;
    const int block_row = blockIdx.x * 128;

    float acc[2][8][4];
#pragma unroll
    for (int mt = 0; mt < 2; mt++)
#pragma unroll
        for (int g = 0; g < 8; g++)
#pragma unroll
            for (int c = 0; c < 4; c++) acc[mt][g][c] = 0.f;

    float4 va[8], vbw[8];
    load_a_regs(va, feat, block_row, 0, tid, N);
    load_b_regs(vbw, weight, 0, tid);
    store_a(smem, va, tid);
    store_b(smem, vbw, tid);
    __syncthreads();

    for (int pass = 0; pass < 4; pass++) {
        const uint32_t sbc = sb + (uint32_t)(pass & 1) * BUF;

        if (pass < 3) {
            load_a_regs(va, feat, block_row, (pass + 1) * KT, tid, N);
            load_b_regs(vbw, weight, (pass + 1) * KT, tid);
        }

#pragma unroll
        for (int ks = 0; ks < 4; ks++) {
            uint32_t a0[2][4], a1[2][4];
#pragma unroll
            for (int mt = 0; mt < 2; mt++) {
                int row = mw * 32 + mt * 16 + (lane & 15);
                int chunk = ks * 2 + (lane >> 4);
                uint32_t off = (uint32_t)row * 128 + (uint32_t)((chunk ^ (row & 7)) << 4);
                ldm_x4(a0[mt], sbc + SA0 + off);
                ldm_x4(a1[mt], sbc + SA1 + off);
            }
            uint32_t b0[8][2], b1[8][2];
#pragma unroll
            for (int g16 = 0; g16 < 4; g16++) {
                int t = lane >> 3;
                int krow = ks * 16 + ((t & 1) << 3) + (lane & 7);
                int chunk = nw * 8 + g16 * 2 + (t >> 1);
                uint32_t off = (uint32_t)krow * 256 + (uint32_t)((chunk ^ (krow & 7)) << 4);
                uint32_t r0[4], r1[4];
                ldm_x4_t(r0, sbc + SB0 + off);
                ldm_x4_t(r1, sbc + SB1 + off);
                b0[g16 * 2 + 0][0] = r0[0]; b0[g16 * 2 + 0][1] = r0[1];
                b0[g16 * 2 + 1][0] = r0[2]; b0[g16 * 2 + 1][1] = r0[3];
                b1[g16 * 2 + 0][0] = r1[0]; b1[g16 * 2 + 0][1] = r1[1];
                b1[g16 * 2 + 1][0] = r1[2]; b1[g16 * 2 + 1][1] = r1[3];
            }
#pragma unroll
            for (int mt = 0; mt < 2; mt++)
#pragma unroll
                for (int g = 0; g < 8; g++) {
                    mma_bf16(acc[mt][g], a0[mt], b0[g][0], b0[g][1]);
                    mma_bf16(acc[mt][g], a0[mt], b1[g][0], b1[g][1]);
                    mma_bf16(acc[mt][g], a1[mt], b0[g][0], b0[g][1]);
                }
        }

        if (pass < 3) {
            char* nxt = smem + ((pass + 1) & 1) * BUF;
            store_a(nxt, va, tid);
            store_b(nxt, vbw, tid);
        }
        __syncthreads();
    }

    // ---- epilogue: store UNnormalized fp16 h ----
#pragma unroll
    for (int mt = 0; mt < 2; mt++) {
        int row0 = block_row + mw * 32 + mt * 16 + (lane >> 2);
        int row1 = row0 + 8;
#pragma unroll
        for (int g = 0; g < 8; g++) {
            int col = nw * 64 + g * 8 + (lane & 3) * 2;
            if (row0 < N)
                *(__half2*)(g_h + (size_t)row0 * OUT_F + col) =
                    __floats2half2_rn(acc[mt][g][0], acc[mt][g][1]);
            if (row1 < N)
                *(__half2*)(g_h + (size_t)row1 * OUT_F + col) =
                    __floats2half2_rn(acc[mt][g][2], acc[mt][g][3]);
        }
    }
}

// ---------------------------------------------------------------------------
// Join Kernel: gather  out[n] = sum_{e: dst=n} h[src[e]]*norm[src[e]] + bias
// Segment of node n: [g_off[n], g_off[n] + g_cnt[n])
// ---------------------------------------------------------------------------
__device__ __forceinline__ void acc_row(float4& acc, int s, int lane) {
    float nrm = g_norm[s];
    uint2 u = *((const uint2*)(g_h + (size_t)s * OUT_F) + lane);
    float2 f0 = __half22float2(*(__half2*)&u.x);
    float2 f1 = __half22float2(*(__half2*)&u.y);
    acc.x += f0.x * nrm; acc.y += f0.y * nrm;
    acc.z += f1.x * nrm; acc.w += f1.y * nrm;
}

__global__ void __launch_bounds__(256)
gather_kernel(const float* __restrict__ bias, float* __restrict__ out, int N) {
    const int lane = threadIdx.x & 31;
    const int node = (blockIdx.x * blockDim.x + threadIdx.x) >> 5;
    if (node >= N) return;
    const int beg = g_off[node];
    const int end = beg + g_cnt[node];

    float4 acc = make_float4(0.f, 0.f, 0.f, 0.f);
    for (int b = beg; b < end; b += 32) {
        int idx = b + lane;
        int s = (idx < end) ? g_srcs[idx] : 0;
        int cnt = end - b; if (cnt > 32) cnt = 32;
        int j = 0;
        for (; j + 4 <= cnt; j += 4) {
            int s0 = __shfl_sync(0xffffffffu, s, j + 0);
            int s1 = __shfl_sync(0xffffffffu, s, j + 1);
            int s2 = __shfl_sync(0xffffffffu, s, j + 2);
            int s3 = __shfl_sync(0xffffffffu, s, j + 3);
            acc_row(acc, s0, lane);
            acc_row(acc, s1, lane);
            acc_row(acc, s2, lane);
            acc_row(acc, s3, lane);
        }
        for (; j < cnt; j++) {
            int sj = __shfl_sync(0xffffffffu, s, j);
            acc_row(acc, sj, lane);
        }
    }
    float4 b4 = *((const float4*)bias + lane);
    *((float4*)(out + (size_t)node * OUT_F) + lane) =
        make_float4(acc.x + b4.x, acc.y + b4.y, acc.z + b4.z, acc.w + b4.w);
}

// ---------------------------------------------------------------------------
extern "C" void kernel_launch(void* const* d_in, const int* in_sizes, int n_in,
                              void* d_out, int out_size) {
    const float* feat   = (const float*)d_in[0];
    const float* weight = (const float*)d_in[1];
    const float* bias   = (const float*)d_in[2];
    const int*   src    = (const int*)d_in[3];
    const int*   dst    = (const int*)d_in[4];
    float* out = (float*)d_out;

    const int N = in_sizes[0] / IN_F;   // 50000
    const int E = in_sizes[3];          // 800000
    const int nb = (N + SCAN_B - 1) / SCAN_B;

    // One-time resource setup (host-side objects only; no device memory).
    static cudaStream_t sB = nullptr;
    static cudaEvent_t evFork = nullptr, evCSR = nullptr;
    if (sB == nullptr) {
        cudaStreamCreateWithFlags(&sB, cudaStreamNonBlocking);
        cudaEventCreateWithFlags(&evFork, cudaEventDisableTiming);
        cudaEventCreateWithFlags(&evCSR, cudaEventDisableTiming);
        cudaFuncSetAttribute(gemm_hmma_kernel,
                             cudaFuncAttributeMaxDynamicSharedMemorySize, GEMM_SMEM);
    }

    // Fork: CSR chain on sB, GEMM on the capture (default) stream.
    cudaEventRecord(evFork, 0);
    cudaStreamWaitEvent(sB, evFork, 0);

    zero_kernel<<<256, 256, 0, sB>>>(N);
    edge_count_kernel<<<1024, 256, 0, sB>>>(src, dst, E);
    scan_kernel<<<nb, SCAN_B, 0, sB>>>(N);
    bucket_kernel<<<1024, 256, 0, sB>>>(src, dst, E);
    cudaEventRecord(evCSR, sB);

    gemm_hmma_kernel<<<(N + 127) / 128, 256, GEMM_SMEM>>>(feat, weight, N);

    // Join: gather needs g_h (stream 0) + CSR/norm (sB).
    cudaStreamWaitEvent(0, evCSR, 0);
    gather_kernel<<<(N * 32 + 255) / 256, 256>>>(bias, out, N);
}